// round 1
// baseline (speedup 1.0000x reference)
#include <cuda_runtime.h>
#include <math.h>

// Problem constants (fixed-shape problem: S=T=4, D=H=DT=128, N=65536)
#define NS 4
#define NT 4
#define DK 128
#define NMAX 65536
#define TM 128
#define STRIDE 132          // smem row stride (floats) for X/H tiles: 16B-aligned rows, conflict-friendly
#define NTHREADS 256

// -------- device-side scratch (no allocations allowed) --------
__device__ int   d_best_t[NS];
__device__ float d_best_prob[NS];
__device__ int   d_counts[NS];
__device__ int   d_offsets[NS + 1];
__device__ int   d_cursor[NS];
__device__ int   d_tiles[NS + 1];
__device__ int   d_perm[NMAX];

// -------- f32x2 helpers (Blackwell packed fp32 FMA) --------
__device__ __forceinline__ unsigned long long packdup(float x) {
    unsigned long long r;
    unsigned u = __float_as_uint(x);
    asm("mov.b64 %0, {%1, %1};" : "=l"(r) : "r"(u));
    return r;
}
__device__ __forceinline__ unsigned long long fma2(unsigned long long a,
                                                   unsigned long long b,
                                                   unsigned long long c) {
    unsigned long long d;
    asm("fma.rn.f32x2 %0, %1, %2, %3;" : "=l"(d) : "l"(a), "l"(b), "l"(c));
    return d;
}
__device__ __forceinline__ float2 unpack2(unsigned long long v) {
    unsigned lo, hi;
    asm("mov.b64 {%0, %1}, %2;" : "=r"(lo), "=r"(hi) : "l"(v));
    return make_float2(__uint_as_float(lo), __uint_as_float(hi));
}

// ============================================================
// Kernel 1: argmax over T per source type + sigmoid(best); zero counters
// ============================================================
__global__ void setup_kernel(const float* __restrict__ type_matching) {
    int s = threadIdx.x;
    if (s < NS) {
        float best = type_matching[s * NT];
        int bt = 0;
        for (int t = 1; t < NT; t++) {
            float v = type_matching[s * NT + t];
            if (v > best) { best = v; bt = t; }   // first-max tie-break like argmax
        }
        d_best_t[s] = bt;
        d_best_prob[s] = 1.0f / (1.0f + expf(-best));
        d_counts[s] = 0;
    }
}

// ============================================================
// Kernel 2: warp-aggregated per-type counting
// ============================================================
__global__ void count_kernel(const int* __restrict__ tids, int n) {
    int stride = gridDim.x * blockDim.x;
    int lane = threadIdx.x & 31;
    for (int i = blockIdx.x * blockDim.x + threadIdx.x;
         __any_sync(0xffffffffu, i < n); i += stride) {
        bool valid = i < n;
        unsigned act = __ballot_sync(0xffffffffu, valid);
        if (valid) {
            int s = tids[i];
            unsigned peers = __match_any_sync(act, s);
            int leader = __ffs(peers) - 1;
            if (lane == leader) atomicAdd(&d_counts[s], __popc(peers));
        }
    }
}

// ============================================================
// Kernel 3: exclusive scan (S=4), tile starts, cursor init
// ============================================================
__global__ void offsets_kernel() {
    if (threadIdx.x == 0 && blockIdx.x == 0) {
        int off = 0, ts = 0;
        for (int s = 0; s < NS; s++) {
            d_offsets[s] = off;
            d_cursor[s]  = off;
            d_tiles[s]   = ts;
            ts  += (d_counts[s] + TM - 1) / TM;
            off += d_counts[s];
        }
        d_offsets[NS] = off;
        d_tiles[NS]   = ts;
    }
}

// ============================================================
// Kernel 4: warp-aggregated scatter into per-type index lists
// ============================================================
__global__ void scatter_kernel(const int* __restrict__ tids, int n) {
    int stride = gridDim.x * blockDim.x;
    int lane = threadIdx.x & 31;
    for (int i = blockIdx.x * blockDim.x + threadIdx.x;
         __any_sync(0xffffffffu, i < n); i += stride) {
        bool valid = i < n;
        unsigned act = __ballot_sync(0xffffffffu, valid);
        if (valid) {
            int s = tids[i];
            unsigned peers = __match_any_sync(act, s);
            int leader = __ffs(peers) - 1;
            int rank = __popc(peers & ((1u << lane) - 1u));
            int base = 0;
            if (lane == leader) base = atomicAdd(&d_cursor[s], __popc(peers));
            base = __shfl_sync(act, base, leader);
            d_perm[base + rank] = i;
        }
    }
}

// ============================================================
// 128x128x128 fp32 GEMM core with f32x2 FMA.
// A is a [128][STRIDE] smem tile (row = item, col = k).
// B is a [128][128] row-major global matrix (k-major rows), streamed through
// a double-buffered 16x128 smem tile. Each thread owns 8 items x 8 cols.
// ============================================================
__device__ __forceinline__ void gemm128(const float* __restrict__ As,
                                        const float* __restrict__ Bglob,
                                        float* __restrict__ Wt,
                                        unsigned long long (&acc)[8][4],
                                        int tx, int ty, int tid) {
#pragma unroll
    for (int i = 0; i < 8; i++)
#pragma unroll
        for (int j = 0; j < 4; j++) acc[i][j] = 0ull;

    int lr = tid >> 4;          // 0..15: row within the 16-row B tile
    int lc = (tid & 15) << 3;   // 0..120: 8-float column slab

    // prime buffer 0
    {
        const float* src = Bglob + lr * DK + lc;
        float4 p0 = *(const float4*)src;
        float4 p1 = *(const float4*)(src + 4);
        *(float4*)(Wt + lr * DK + lc) = p0;
        *(float4*)(Wt + lr * DK + lc + 4) = p1;
    }
    __syncthreads();

    float4 p0, p1;
#pragma unroll 1
    for (int kt = 0; kt < 8; kt++) {
        if (kt < 7) {   // prefetch next tile into registers (overlaps compute)
            const float* src = Bglob + ((kt + 1) * 16 + lr) * DK + lc;
            p0 = *(const float4*)src;
            p1 = *(const float4*)(src + 4);
        }
        const float* W = Wt + (kt & 1) * 16 * DK;
#pragma unroll
        for (int k = 0; k < 16; k++) {
            ulonglong2 bA = *(const ulonglong2*)(W + k * DK + tx * 8);
            ulonglong2 bB = *(const ulonglong2*)(W + k * DK + tx * 8 + 4);
#pragma unroll
            for (int i = 0; i < 8; i++) {
                unsigned long long ad =
                    packdup(As[(ty * 8 + i) * STRIDE + kt * 16 + k]);
                acc[i][0] = fma2(ad, bA.x, acc[i][0]);
                acc[i][1] = fma2(ad, bA.y, acc[i][1]);
                acc[i][2] = fma2(ad, bB.x, acc[i][2]);
                acc[i][3] = fma2(ad, bB.y, acc[i][3]);
            }
        }
        __syncthreads();
        if (kt < 7) {
            int nb = (kt + 1) & 1;
            *(float4*)(Wt + nb * 16 * DK + lr * DK + lc) = p0;
            *(float4*)(Wt + nb * 16 * DK + lr * DK + lc + 4) = p1;
            __syncthreads();
        }
    }
}

// ============================================================
// Kernel 5: fused per-tile expert MLP + classifier + scatter epilogue
// ============================================================
__global__ __launch_bounds__(NTHREADS, 1)
void fused_kernel(const float* __restrict__ states,
                  const float* __restrict__ scores,
                  const float* __restrict__ W1, const float* __restrict__ b1,
                  const float* __restrict__ W2, const float* __restrict__ b2,
                  const float* __restrict__ C1, const float* __restrict__ c1,
                  const float* __restrict__ C2, const float* __restrict__ c2,
                  float* __restrict__ out, int n) {
    extern __shared__ float sm[];
    float* Xs  = sm;                      // TM*STRIDE
    float* Hs  = Xs + TM * STRIDE;        // TM*STRIDE
    float* Wt  = Hs + TM * STRIDE;        // 2*16*DK
    float* red = Wt + 2 * 16 * DK;        // TM*17
    float* b1s = red + TM * 17;           // DK
    float* b2s = b1s + DK;                // DK
    float* c1s = b2s + DK;                // DK
    float* c2v = c1s + DK;                // DK

    int b = blockIdx.x;
    if (b >= d_tiles[NS]) return;
    int s = 0;
#pragma unroll
    for (int i = 1; i < NS; i++)
        if (b >= d_tiles[i]) s = i;
    int tile = b - d_tiles[s];
    int row0 = d_offsets[s] + tile * TM;
    int rows = min(TM, d_offsets[s + 1] - row0);
    int sel = s * NT + d_best_t[s];

    const float* W1p = W1 + (size_t)sel * DK * DK;
    const float* W2p = W2 + (size_t)sel * DK * DK;
    const float* C1p = C1 + (size_t)sel * DK * DK;

    int tid = threadIdx.x;
    int tx = tid & 15, ty = tid >> 4;

    if (tid < DK) {
        b1s[tid] = b1[sel * DK + tid];
        b2s[tid] = b2[sel * DK + tid];
        c1s[tid] = c1[sel * DK + tid];
        c2v[tid] = C2[(size_t)sel * DK + tid];
    }
    float c2sc  = c2[sel];
    float bprob = d_best_prob[s];

    // gather X tile (zero-pad tail rows for determinism)
    for (int v = tid; v < TM * 32; v += NTHREADS) {
        int r = v >> 5, c4 = (v & 31) << 2;
        float4 val = make_float4(0.f, 0.f, 0.f, 0.f);
        if (r < rows) {
            int g = d_perm[row0 + r];
            val = *(const float4*)(states + (size_t)g * DK + c4);
        }
        *(float4*)(Xs + r * STRIDE + c4) = val;
    }
    __syncthreads();

    unsigned long long acc[8][4];

    // ---- Pass 1: H = relu(X @ W1 + b1) -> Hs ----
    gemm128(Xs, W1p, Wt, acc, tx, ty, tid);
#pragma unroll
    for (int i = 0; i < 8; i++) {
        int r = ty * 8 + i;
#pragma unroll
        for (int j = 0; j < 4; j++) {
            int c = tx * 8 + j * 2;
            float2 v = unpack2(acc[i][j]);
            v.x = fmaxf(v.x + b1s[c], 0.f);
            v.y = fmaxf(v.y + b1s[c + 1], 0.f);
            *(float2*)(Hs + r * STRIDE + c) = v;
        }
    }
    __syncthreads();

    // ---- Pass 2: classifier  cls = sigmoid(relu(X @ C1 + c1) . C2 + c2) ----
    gemm128(Xs, C1p, Wt, acc, tx, ty, tid);
#pragma unroll
    for (int i = 0; i < 8; i++) {
        int r = ty * 8 + i;
        float p = 0.f;
#pragma unroll
        for (int j = 0; j < 4; j++) {
            int c = tx * 8 + j * 2;
            float2 v = unpack2(acc[i][j]);
            p += fmaxf(v.x + c1s[c], 0.f) * c2v[c];
            p += fmaxf(v.y + c1s[c + 1], 0.f) * c2v[c + 1];
        }
        red[r * 17 + tx] = p;
    }
    __syncthreads();
    if (tid < TM) {
        int r = tid;
        float sum = 0.f;
#pragma unroll
        for (int j = 0; j < 16; j++) sum += red[r * 17 + j];
        if (r < rows) {
            int g = d_perm[row0 + r];
            float cls = 1.0f / (1.0f + expf(-(sum + c2sc)));
            float ns = fminf(scores[g], cls);
            out[(size_t)n * DK + g]     = ns;     // out_score
            out[(size_t)n * DK + n + g] = bprob;  // item_prob
        }
    }
    __syncthreads();

    // ---- Pass 3: Y = H @ W2 + b2 -> scatter to out_state ----
    gemm128(Hs, W2p, Wt, acc, tx, ty, tid);
#pragma unroll
    for (int i = 0; i < 8; i++) {
        int r = ty * 8 + i;
        if (r < rows) {
            int g = d_perm[row0 + r];
#pragma unroll
            for (int jj = 0; jj < 2; jj++) {
                float2 v0 = unpack2(acc[i][jj * 2]);
                float2 v1 = unpack2(acc[i][jj * 2 + 1]);
                int c = tx * 8 + jj * 4;
                float4 o = make_float4(v0.x + b2s[c], v0.y + b2s[c + 1],
                                       v1.x + b2s[c + 2], v1.y + b2s[c + 3]);
                *(float4*)(out + (size_t)g * DK + c) = o;
            }
        }
    }
}

// ============================================================
// launch
// ============================================================
extern "C" void kernel_launch(void* const* d_in, const int* in_sizes, int n_in,
                              void* d_out, int out_size) {
    const float* states = (const float*)d_in[0];
    const float* scores = (const float*)d_in[1];
    const int*   tids   = (const int*)d_in[2];
    const float* tmatch = (const float*)d_in[3];
    const float* W1 = (const float*)d_in[4];
    const float* b1 = (const float*)d_in[5];
    const float* W2 = (const float*)d_in[6];
    const float* b2 = (const float*)d_in[7];
    const float* C1 = (const float*)d_in[8];
    const float* c1 = (const float*)d_in[9];
    const float* C2 = (const float*)d_in[10];
    const float* c2 = (const float*)d_in[11];
    float* out = (float*)d_out;
    int n = in_sizes[2];

    const int smem_bytes = (2 * TM * STRIDE + 2 * 16 * DK + TM * 17 + 4 * DK) *
                           (int)sizeof(float);
    cudaFuncSetAttribute(fused_kernel,
                         cudaFuncAttributeMaxDynamicSharedMemorySize, smem_bytes);

    setup_kernel<<<1, 32>>>(tmatch);
    count_kernel<<<128, 256>>>(tids, n);
    offsets_kernel<<<1, 32>>>();
    scatter_kernel<<<128, 256>>>(tids, n);

    int max_tiles = NMAX / TM + NS;  // device-side early-exit trims to actual
    fused_kernel<<<max_tiles, NTHREADS, smem_bytes>>>(
        states, scores, W1, b1, W2, b2, C1, c1, C2, c2, out, n);
}

// round 6
// speedup vs baseline: 2.0855x; 2.0855x over previous
#include <cuda_runtime.h>
#include <cuda_bf16.h>
#include <math.h>
#include <stdint.h>

// Fixed-shape problem: S=T=4, D=H=DT=128, N=65536
#define NS 4
#define NT 4
#define DK 128
#define NMAX 65536
#define TM 128
#define NTH 256
#define SBB 272                  // smem tile row stride in BYTES (136 bf16) — ldmatrix conflict-free
#define TILEB (128 * SBB)        // 34816 bytes per bf16 tile

// ---------------- device scratch (no allocations allowed) ----------------
__device__ int   d_best_t[NS];
__device__ float d_best_prob[NS];
__device__ int   d_counts[NS];
__device__ int   d_offsets[NS + 1];
__device__ int   d_cursor[NS];
__device__ int   d_tiles[NS + 1];
__device__ int   d_perm[NMAX];
// 4 experts x 3 mats (W1,C1,W2) x 2 halves (hi,lo), packed Bt[n][k] bf16 128x128 = 32KB
__device__ __align__(16) unsigned char d_wbuf[4 * 3 * 2 * 32768];

// ---------------- helpers ----------------
__device__ __forceinline__ uint32_t smem_u32(const void* p) {
    uint32_t a;
    asm("{ .reg .u64 t; cvta.to.shared.u64 t, %1; cvt.u32.u64 %0, t; }"
        : "=r"(a) : "l"(p));
    return a;
}
__device__ __forceinline__ void ldsm4(uint32_t& r0, uint32_t& r1, uint32_t& r2,
                                      uint32_t& r3, uint32_t a) {
    asm volatile("ldmatrix.sync.aligned.m8n8.x4.shared.b16 {%0,%1,%2,%3}, [%4];"
                 : "=r"(r0), "=r"(r1), "=r"(r2), "=r"(r3) : "r"(a));
}
__device__ __forceinline__ void mma16816(float* d, const uint32_t* a,
                                         const uint32_t* b) {
    asm volatile(
        "mma.sync.aligned.m16n8k16.row.col.f32.bf16.bf16.f32 "
        "{%0,%1,%2,%3},{%4,%5,%6,%7},{%8,%9},{%0,%1,%2,%3};"
        : "+f"(d[0]), "+f"(d[1]), "+f"(d[2]), "+f"(d[3])
        : "r"(a[0]), "r"(a[1]), "r"(a[2]), "r"(a[3]), "r"(b[0]), "r"(b[1]));
}
// split fp32 pair -> (hi bf16x2, lo bf16x2)
__device__ __forceinline__ void split2(float x0, float x1, uint32_t& hi, uint32_t& lo) {
    __nv_bfloat162 h = __floats2bfloat162_rn(x0, x1);
    hi = *reinterpret_cast<uint32_t*>(&h);
    float h0 = __uint_as_float(hi << 16);
    float h1 = __uint_as_float(hi & 0xffff0000u);
    __nv_bfloat162 l = __floats2bfloat162_rn(x0 - h0, x1 - h1);
    lo = *reinterpret_cast<uint32_t*>(&l);
}

// ============================================================
// setup: per-type argmax + sigmoid; reset counters
// ============================================================
__global__ void setup_kernel(const float* __restrict__ tm) {
    int s = threadIdx.x;
    if (s < NS) {
        float best = tm[s * NT];
        int bt = 0;
        for (int t = 1; t < NT; t++) {
            float v = tm[s * NT + t];
            if (v > best) { best = v; bt = t; }
        }
        d_best_t[s] = bt;
        d_best_prob[s] = 1.0f / (1.0f + expf(-best));
        d_counts[s] = 0;
    }
}

// ============================================================
// prep: selected expert weights -> bf16 hi/lo, transposed to Bt[n][k], packed
// grid: 4 experts x 3 mats x 4 quarters = 48 blocks x 256 threads
// ============================================================
__global__ void prep_kernel(const float* __restrict__ W1,
                            const float* __restrict__ C1,
                            const float* __restrict__ W2) {
    int blk = blockIdx.x;
    int e = blk / 12, rem = blk % 12;
    int m = rem >> 2, q = rem & 3;
    int sel = e * NT + d_best_t[e];
    const float* src = (m == 0 ? W1 : (m == 1 ? C1 : W2)) + (size_t)sel * 16384;
    unsigned char* dhi = d_wbuf + (size_t)((e * 3 + m) * 2 + 0) * 32768;
    unsigned char* dlo = dhi + 32768;
#pragma unroll 4
    for (int i = 0; i < 16; i++) {
        int idx = q * 4096 + i * 256 + threadIdx.x;
        float x = src[idx];
        int k = idx >> 7, nn = idx & 127;          // src is [k][n]; dst Bt[n][k]
        uint32_t off = (uint32_t)(nn * 128 + k) * 2;
        __nv_bfloat16 h = __float2bfloat16(x);
        float hf = __bfloat162float(h);
        __nv_bfloat16 l = __float2bfloat16(x - hf);
        *(__nv_bfloat16*)(dhi + off) = h;
        *(__nv_bfloat16*)(dlo + off) = l;
    }
}

// ============================================================
// count / offsets / scatter (block-aggregated)
// ============================================================
__global__ void count_kernel(const int* __restrict__ tids, int n) {
    __shared__ int h[NS];
    if (threadIdx.x < NS) h[threadIdx.x] = 0;
    __syncthreads();
    int i = blockIdx.x * blockDim.x + threadIdx.x;
    if (i < n) atomicAdd(&h[tids[i]], 1);
    __syncthreads();
    if (threadIdx.x < NS && h[threadIdx.x]) atomicAdd(&d_counts[threadIdx.x], h[threadIdx.x]);
}

__global__ void offsets_kernel() {
    if (threadIdx.x == 0 && blockIdx.x == 0) {
        int off = 0, ts = 0;
        for (int s = 0; s < NS; s++) {
            d_offsets[s] = off;
            d_cursor[s] = off;
            d_tiles[s] = ts;
            ts += (d_counts[s] + TM - 1) / TM;
            off += d_counts[s];
        }
        d_offsets[NS] = off;
        d_tiles[NS] = ts;
    }
}

__global__ void scatter_kernel(const int* __restrict__ tids, int n) {
    __shared__ int h[NS], base[NS];
    if (threadIdx.x < NS) h[threadIdx.x] = 0;
    __syncthreads();
    int i = blockIdx.x * blockDim.x + threadIdx.x;
    int s = -1, rank = 0;
    if (i < n) { s = tids[i]; rank = atomicAdd(&h[s], 1); }
    __syncthreads();
    if (threadIdx.x < NS && h[threadIdx.x])
        base[threadIdx.x] = atomicAdd(&d_cursor[threadIdx.x], h[threadIdx.x]);
    __syncthreads();
    if (s >= 0) d_perm[base[s] + rank] = i;
}

// ============================================================
// SMEM layout (dynamic, bytes)
// ============================================================
static const int SM_B1  = 0;
static const int SM_B2  = 512;
static const int SM_C1  = 1024;
static const int SM_C2V = 1536;
static const int SM_CLS = 2048;                 // 2 x 128 floats
static const int SM_XHI = 3072;
static const int SM_XLO = SM_XHI + TILEB;
static const int SM_HHI = SM_XLO + TILEB;
static const int SM_HLO = SM_HHI + TILEB;
static const int SM_WHI = SM_HLO + TILEB;
static const int SM_WLO = SM_WHI + TILEB;
static const int SM_TOTAL = SM_WLO + TILEB;     // 211968 bytes

// copy one packed 32KB hi/lo pair into padded smem tiles
__device__ __forceinline__ void copy_w(unsigned char* smem, int s, int m, int tid) {
    const uint4* sh = (const uint4*)(d_wbuf + (size_t)((s * 3 + m) * 2 + 0) * 32768);
    const uint4* sl = (const uint4*)(d_wbuf + (size_t)((s * 3 + m) * 2 + 1) * 32768);
#pragma unroll
    for (int i = tid; i < 2048; i += NTH) {
        int row = i >> 4, c16 = i & 15;               // 16 x 16B chunks per 128-bf16 row
        uint32_t off = row * SBB + c16 * 16;
        *(uint4*)(smem + SM_WHI + off) = sh[i];
        *(uint4*)(smem + SM_WLO + off) = sl[i];
    }
}

// 128x128x128 bf16 hi/lo 3-mma GEMM pass; acc[mt][ng][4] fp32
__device__ __forceinline__ void gemm_pass(uint32_t Ahi, uint32_t Alo,
                                          uint32_t Bhi, uint32_t Blo,
                                          float acc[2][8][4],
                                          int wm, int wn, int lane) {
#pragma unroll
    for (int mt = 0; mt < 2; mt++)
#pragma unroll
        for (int ng = 0; ng < 8; ng++)
#pragma unroll
            for (int i = 0; i < 4; i++) acc[mt][ng][i] = 0.f;

    uint32_t a_row = (lane & 15);
    uint32_t a_c8 = (lane >> 4);
    uint32_t b_n = (lane & 7) + ((lane >> 4) << 3);
    uint32_t b_c8 = (lane >> 3) & 1;

#pragma unroll
    for (int ks = 0; ks < 8; ks++) {
        uint32_t kb = ks * 32;                         // 16 elems * 2B
        uint32_t aoff = (wm * 32 + a_row) * SBB + kb + a_c8 * 16;
        uint32_t ah[2][4], al[2][4];
        ldsm4(ah[0][0], ah[0][1], ah[0][2], ah[0][3], Ahi + aoff);
        ldsm4(ah[1][0], ah[1][1], ah[1][2], ah[1][3], Ahi + aoff + 16 * SBB);
        ldsm4(al[0][0], al[0][1], al[0][2], al[0][3], Alo + aoff);
        ldsm4(al[1][0], al[1][1], al[1][2], al[1][3], Alo + aoff + 16 * SBB);
#pragma unroll
        for (int np = 0; np < 4; np++) {               // pair of n8 groups
            uint32_t boff = (wn * 64 + np * 16 + b_n) * SBB + kb + b_c8 * 16;
            uint32_t bh[4], bl[4];
            ldsm4(bh[0], bh[1], bh[2], bh[3], Bhi + boff);
            ldsm4(bl[0], bl[1], bl[2], bl[3], Blo + boff);
#pragma unroll
            for (int mt = 0; mt < 2; mt++) {
#pragma unroll
                for (int sb = 0; sb < 2; sb++) {
                    float* d = acc[mt][np * 2 + sb];
                    mma16816(d, ah[mt], bh + sb * 2);
                    mma16816(d, ah[mt], bl + sb * 2);
                    mma16816(d, al[mt], bh + sb * 2);
                }
            }
        }
    }
}

// ============================================================
// main fused tile kernel
// ============================================================
__global__ __launch_bounds__(NTH, 1)
void mlp_kernel(const float* __restrict__ states,
                const float* __restrict__ scores,
                const float* __restrict__ b1g, const float* __restrict__ b2g,
                const float* __restrict__ c1g,
                const float* __restrict__ C2g, const float* __restrict__ c2g,
                float* __restrict__ out, int n) {
    extern __shared__ unsigned char smem[];
    int b = blockIdx.x;
    if (b >= d_tiles[NS]) return;

    int tid = threadIdx.x;
    int wid = tid >> 5, lane = tid & 31;
    int wm = wid & 3, wn = wid >> 2;        // warp quadrant: rows 32*wm, cols 64*wn
    int gID = lane >> 2, tig = lane & 3;

    float* b1s = (float*)(smem + SM_B1);
    float* b2s = (float*)(smem + SM_B2);
    float* c1s = (float*)(smem + SM_C1);
    float* c2v = (float*)(smem + SM_C2V);
    float* cls = (float*)(smem + SM_CLS);
    uint32_t Xhi = smem_u32(smem + SM_XHI), Xlo = smem_u32(smem + SM_XLO);
    uint32_t Hhi = smem_u32(smem + SM_HHI), Hlo = smem_u32(smem + SM_HLO);
    uint32_t Whi = smem_u32(smem + SM_WHI), Wlo = smem_u32(smem + SM_WLO);

    // which type / tile
    int s = 0;
#pragma unroll
    for (int i = 1; i < NS; i++)
        if (b >= d_tiles[i]) s = i;
    int row0 = d_offsets[s] + (b - d_tiles[s]) * TM;
    int rows = min(TM, d_offsets[s + 1] - row0);
    int sel = s * NT + d_best_t[s];
    float bprob = d_best_prob[s];
    float c2sc = c2g[sel];

    if (tid < DK) {
        b1s[tid] = b1g[sel * DK + tid];
        b2s[tid] = b2g[sel * DK + tid];
        c1s[tid] = c1g[sel * DK + tid];
        c2v[tid] = C2g[(size_t)sel * DK + tid];
    }

    // W1 into smem + gather X -> bf16 hi/lo padded tiles
    copy_w(smem, s, 0, tid);
    {
        int xr = tid >> 1, xh = tid & 1;
        bool valid = xr < rows;
        int g = valid ? d_perm[row0 + xr] : 0;
        const float4* src = (const float4*)(states + (size_t)g * DK + xh * 64);
        uint32_t base0 = xr * SBB + xh * 128;
#pragma unroll
        for (int j8 = 0; j8 < 8; j8++) {
            float4 a = valid ? src[j8 * 2] : make_float4(0, 0, 0, 0);
            float4 c = valid ? src[j8 * 2 + 1] : make_float4(0, 0, 0, 0);
            uint4 hi, lo;
            split2(a.x, a.y, hi.x, lo.x);
            split2(a.z, a.w, hi.y, lo.y);
            split2(c.x, c.y, hi.z, lo.z);
            split2(c.z, c.w, hi.w, lo.w);
            uint32_t off = base0 + j8 * 16;
            *(uint4*)(smem + SM_XHI + off) = hi;
            *(uint4*)(smem + SM_XLO + off) = lo;
        }
    }
    __syncthreads();

    float acc[2][8][4];

    // ================= Pass 1: D = X @ W1, H = relu(D + b1) =================
    gemm_pass(Xhi, Xlo, Whi, Wlo, acc, wm, wn, lane);
    __syncthreads();               // all warps done reading W1 tile
    copy_w(smem, s, 1, tid);       // C1 into W tile (disjoint from H writes)
#pragma unroll
    for (int mt = 0; mt < 2; mt++) {
#pragma unroll
        for (int rh = 0; rh < 2; rh++) {
            int r = wm * 32 + mt * 16 + rh * 8 + gID;
            uint32_t roff = r * SBB;
#pragma unroll
            for (int ng = 0; ng < 8; ng++) {
                int c = wn * 64 + ng * 8 + 2 * tig;
                float v0 = fmaxf(acc[mt][ng][rh * 2 + 0] + b1s[c], 0.f);
                float v1 = fmaxf(acc[mt][ng][rh * 2 + 1] + b1s[c + 1], 0.f);
                uint32_t hi, lo;
                split2(v0, v1, hi, lo);
                uint32_t off = roff + c * 2;
                *(uint32_t*)(smem + SM_HHI + off) = hi;
                *(uint32_t*)(smem + SM_HLO + off) = lo;
            }
        }
    }
    __syncthreads();

    // ================= Pass 2: D = X @ C1 (classifier) =================
    gemm_pass(Xhi, Xlo, Whi, Wlo, acc, wm, wn, lane);
#pragma unroll
    for (int mt = 0; mt < 2; mt++) {
#pragma unroll
        for (int rh = 0; rh < 2; rh++) {
            float p = 0.f;
#pragma unroll
            for (int ng = 0; ng < 8; ng++) {
                int c = wn * 64 + ng * 8 + 2 * tig;
                p += fmaxf(acc[mt][ng][rh * 2 + 0] + c1s[c], 0.f) * c2v[c];
                p += fmaxf(acc[mt][ng][rh * 2 + 1] + c1s[c + 1], 0.f) * c2v[c + 1];
            }
            p += __shfl_xor_sync(0xffffffffu, p, 1);
            p += __shfl_xor_sync(0xffffffffu, p, 2);
            if (tig == 0) {
                int r = wm * 32 + mt * 16 + rh * 8 + gID;
                cls[wn * 128 + r] = p;
            }
        }
    }
    __syncthreads();               // cls visible; all warps done reading C1
    copy_w(smem, s, 2, tid);       // W2 into W tile
    if (tid < TM && tid < rows) {
        int g = d_perm[row0 + tid];
        float tot = cls[tid] + cls[128 + tid] + c2sc;
        float cv = 1.0f / (1.0f + expf(-tot));
        float ns = fminf(scores[g], cv);
        out[(size_t)n * DK + g]     = ns;     // out_score
        out[(size_t)n * DK + n + g] = bprob;  // item_prob
    }
    __syncthreads();

    // ================= Pass 3: D = H @ W2, out_state = D + b2 =================
    gemm_pass(Hhi, Hlo, Whi, Wlo, acc, wm, wn, lane);
#pragma unroll
    for (int mt = 0; mt < 2; mt++) {
#pragma unroll
        for (int rh = 0; rh < 2; rh++) {
            int r = wm * 32 + mt * 16 + rh * 8 + gID;
            if (r < rows) {
                int g = d_perm[row0 + r];
                float* dst = out + (size_t)g * DK;
#pragma unroll
                for (int ng = 0; ng < 8; ng++) {
                    int c = wn * 64 + ng * 8 + 2 * tig;
                    float2 v;
                    v.x = acc[mt][ng][rh * 2 + 0] + b2s[c];
                    v.y = acc[mt][ng][rh * 2 + 1] + b2s[c + 1];
                    *(float2*)(dst + c) = v;
                }
            }
        }
    }
}

// ============================================================
// launch
// ============================================================
extern "C" void kernel_launch(void* const* d_in, const int* in_sizes, int n_in,
                              void* d_out, int out_size) {
    const float* states = (const float*)d_in[0];
    const float* scores = (const float*)d_in[1];
    const int*   tids   = (const int*)d_in[2];
    const float* tmatch = (const float*)d_in[3];
    const float* W1 = (const float*)d_in[4];
    const float* b1 = (const float*)d_in[5];
    const float* W2 = (const float*)d_in[6];
    const float* b2 = (const float*)d_in[7];
    const float* C1 = (const float*)d_in[8];
    const float* c1 = (const float*)d_in[9];
    const float* C2 = (const float*)d_in[10];
    const float* c2 = (const float*)d_in[11];
    float* out = (float*)d_out;
    int n = in_sizes[2];

    cudaFuncSetAttribute(mlp_kernel, cudaFuncAttributeMaxDynamicSharedMemorySize, SM_TOTAL);

    int nblk = (n + 255) / 256;
    setup_kernel<<<1, 32>>>(tmatch);
    prep_kernel<<<48, 256>>>(W1, C1, W2);
    count_kernel<<<nblk, 256>>>(tids, n);
    offsets_kernel<<<1, 32>>>();
    scatter_kernel<<<nblk, 256>>>(tids, n);

    int max_tiles = (n + TM - 1) / TM + NS;
    mlp_kernel<<<max_tiles, NTH, SM_TOTAL>>>(states, scores, b1, b2, c1, C2, c2, out, n);
}

// round 7
// speedup vs baseline: 2.8852x; 1.3834x over previous
#include <cuda_runtime.h>
#include <cuda_fp16.h>
#include <math.h>
#include <stdint.h>

// Fixed-shape problem: S=T=4, D=H=DT=128, N=65536
#define NS 4
#define NT 4
#define DK 128
#define NMAX 65536
#define TM 128
#define NTH 256
#define SBB 272                  // smem tile row stride in BYTES (136 fp16) — ldmatrix conflict-free
#define TILEB (128 * SBB)        // 34816 bytes per fp16 tile

// ---------------- device scratch (no allocations allowed) ----------------
__device__ int   d_best_t[NS];
__device__ float d_best_prob[NS];
__device__ int   d_cursor[NS];
__device__ int   d_perm[NS * NMAX];
// 4 experts x 3 mats (W1,C1,W2), fp16, packed Bt[n][k] 128x128 = 32KB each
__device__ __align__(16) unsigned char d_wbuf[4 * 3 * 32768];

// ---------------- helpers ----------------
__device__ __forceinline__ uint32_t smem_u32(const void* p) {
    uint32_t a;
    asm("{ .reg .u64 t; cvta.to.shared.u64 t, %1; cvt.u32.u64 %0, t; }"
        : "=r"(a) : "l"(p));
    return a;
}
__device__ __forceinline__ void ldsm4(uint32_t& r0, uint32_t& r1, uint32_t& r2,
                                      uint32_t& r3, uint32_t a) {
    asm volatile("ldmatrix.sync.aligned.m8n8.x4.shared.b16 {%0,%1,%2,%3}, [%4];"
                 : "=r"(r0), "=r"(r1), "=r"(r2), "=r"(r3) : "r"(a));
}
__device__ __forceinline__ void mma16816(float* d, const uint32_t* a,
                                         const uint32_t* b) {
    asm volatile(
        "mma.sync.aligned.m16n8k16.row.col.f32.f16.f16.f32 "
        "{%0,%1,%2,%3},{%4,%5,%6,%7},{%8,%9},{%0,%1,%2,%3};"
        : "+f"(d[0]), "+f"(d[1]), "+f"(d[2]), "+f"(d[3])
        : "r"(a[0]), "r"(a[1]), "r"(a[2]), "r"(a[3]), "r"(b[0]), "r"(b[1]));
}
// split fp32 pair -> (hi fp16x2, lo fp16x2): a = hi + lo exactly to ~2^-22
__device__ __forceinline__ void split2h(float x0, float x1, uint32_t& hi, uint32_t& lo) {
    __half h0 = __float2half_rn(x0);
    __half h1 = __float2half_rn(x1);
    __half l0 = __float2half_rn(x0 - __half2float(h0));
    __half l1 = __float2half_rn(x1 - __half2float(h1));
    __half2 hp = __halves2half2(h0, h1);
    __half2 lp = __halves2half2(l0, l1);
    hi = *reinterpret_cast<uint32_t*>(&hp);
    lo = *reinterpret_cast<uint32_t*>(&lp);
}

// ============================================================
// setup: per-type argmax + sigmoid; zero cursors
// ============================================================
__global__ void setup_kernel(const float* __restrict__ tm) {
    int s = threadIdx.x;
    if (s < NS) {
        float best = tm[s * NT];
        int bt = 0;
        for (int t = 1; t < NT; t++) {
            float v = tm[s * NT + t];
            if (v > best) { best = v; bt = t; }
        }
        d_best_t[s] = bt;
        d_best_prob[s] = 1.0f / (1.0f + expf(-best));
        d_cursor[s] = 0;
    }
}

// ============================================================
// prep: selected expert weights -> fp16, transposed to Bt[n][k], packed
// grid: 4 experts x 3 mats x 4 quarters = 48 blocks x 256 threads
// ============================================================
__global__ void prep_kernel(const float* __restrict__ W1,
                            const float* __restrict__ C1,
                            const float* __restrict__ W2) {
    int blk = blockIdx.x;
    int e = blk / 12, rem = blk % 12;
    int m = rem >> 2, q = rem & 3;
    int sel = e * NT + d_best_t[e];
    const float* src = (m == 0 ? W1 : (m == 1 ? C1 : W2)) + (size_t)sel * 16384;
    unsigned char* dst = d_wbuf + (size_t)(e * 3 + m) * 32768;
#pragma unroll 4
    for (int i = 0; i < 16; i++) {
        int idx = q * 4096 + i * 256 + threadIdx.x;
        float x = src[idx];
        int k = idx >> 7, nn = idx & 127;          // src is [k][n]; dst Bt[n][k]
        *(__half*)(dst + (uint32_t)(nn * 128 + k) * 2) = __float2half_rn(x);
    }
}

// ============================================================
// scatter: block-aggregated ranks into per-type private perm regions
// ============================================================
__global__ void scatter_kernel(const int* __restrict__ tids, int n) {
    __shared__ int h[NS], base[NS];
    if (threadIdx.x < NS) h[threadIdx.x] = 0;
    __syncthreads();
    int i = blockIdx.x * blockDim.x + threadIdx.x;
    int s = -1, rank = 0;
    if (i < n) { s = tids[i]; rank = atomicAdd(&h[s], 1); }
    __syncthreads();
    if (threadIdx.x < NS && h[threadIdx.x])
        base[threadIdx.x] = atomicAdd(&d_cursor[threadIdx.x], h[threadIdx.x]);
    __syncthreads();
    if (s >= 0) d_perm[s * NMAX + base[s] + rank] = i;
}

// ============================================================
// SMEM layout (dynamic, bytes)
// ============================================================
static const int SM_B1  = 0;
static const int SM_B2  = 512;
static const int SM_C1  = 1024;
static const int SM_C2V = 1536;
static const int SM_CLS = 2048;                 // 2 x 128 floats
static const int SM_XHI = 3072;
static const int SM_XLO = SM_XHI + TILEB;
static const int SM_HH  = SM_XLO + TILEB;
static const int SM_W   = SM_HH + TILEB;
static const int SM_TOTAL = SM_W + TILEB;       // 142336 bytes

// copy one packed 32KB fp16 weight tile into padded smem tile
__device__ __forceinline__ void copy_w(unsigned char* smem, int s, int m, int tid) {
    const uint4* src = (const uint4*)(d_wbuf + (size_t)(s * 3 + m) * 32768);
#pragma unroll
    for (int i = tid; i < 2048; i += NTH) {
        int row = i >> 4, c16 = i & 15;               // 16 x 16B chunks per 128-fp16 row
        *(uint4*)(smem + SM_W + row * SBB + c16 * 16) = src[i];
    }
}

// 128x128x128 fp16 GEMM pass; TERMS=2: (Ahi+Alo)@B, TERMS=1: Ahi@B
template <int TERMS>
__device__ __forceinline__ void gemm_pass(uint32_t Ahi, uint32_t Alo, uint32_t Bt,
                                          float acc[2][8][4],
                                          int wm, int wn, int lane) {
#pragma unroll
    for (int mt = 0; mt < 2; mt++)
#pragma unroll
        for (int ng = 0; ng < 8; ng++)
#pragma unroll
            for (int i = 0; i < 4; i++) acc[mt][ng][i] = 0.f;

    uint32_t a_row = (lane & 15);
    uint32_t a_c8 = (lane >> 4);
    uint32_t b_n = (lane & 7) + ((lane >> 4) << 3);
    uint32_t b_c8 = (lane >> 3) & 1;

#pragma unroll
    for (int ks = 0; ks < 8; ks++) {
        uint32_t kb = ks * 32;                         // 16 elems * 2B
        uint32_t aoff = (wm * 32 + a_row) * SBB + kb + a_c8 * 16;
        uint32_t ah[2][4], al[2][4];
        ldsm4(ah[0][0], ah[0][1], ah[0][2], ah[0][3], Ahi + aoff);
        ldsm4(ah[1][0], ah[1][1], ah[1][2], ah[1][3], Ahi + aoff + 16 * SBB);
        if (TERMS == 2) {
            ldsm4(al[0][0], al[0][1], al[0][2], al[0][3], Alo + aoff);
            ldsm4(al[1][0], al[1][1], al[1][2], al[1][3], Alo + aoff + 16 * SBB);
        }
#pragma unroll
        for (int np = 0; np < 4; np++) {               // pair of n8 groups
            uint32_t boff = (wn * 64 + np * 16 + b_n) * SBB + kb + b_c8 * 16;
            uint32_t bh[4];
            ldsm4(bh[0], bh[1], bh[2], bh[3], Bt + boff);
#pragma unroll
            for (int mt = 0; mt < 2; mt++) {
#pragma unroll
                for (int sb = 0; sb < 2; sb++) {
                    float* d = acc[mt][np * 2 + sb];
                    mma16816(d, ah[mt], bh + sb * 2);
                    if (TERMS == 2) mma16816(d, al[mt], bh + sb * 2);
                }
            }
        }
    }
}

// ============================================================
// main fused tile kernel
// ============================================================
__global__ __launch_bounds__(NTH, 1)
void mlp_kernel(const float* __restrict__ states,
                const float* __restrict__ scores,
                const float* __restrict__ b1g, const float* __restrict__ b2g,
                const float* __restrict__ c1g,
                const float* __restrict__ C2g, const float* __restrict__ c2g,
                float* __restrict__ out, int n, int tps) {
    extern __shared__ unsigned char smem[];
    int s = blockIdx.x / tps;
    int tile = blockIdx.x - s * tps;
    int cnt = d_cursor[s];
    int rows = min(TM, cnt - tile * TM);
    if (rows <= 0) return;
    const int* perm = d_perm + s * NMAX + tile * TM;

    int tid = threadIdx.x;
    int lane = tid & 31;
    int wid = tid >> 5;
    int wm = wid & 3, wn = wid >> 2;        // warp quadrant: rows 32*wm, cols 64*wn
    int gID = lane >> 2, tig = lane & 3;

    float* b1s = (float*)(smem + SM_B1);
    float* b2s = (float*)(smem + SM_B2);
    float* c1s = (float*)(smem + SM_C1);
    float* c2v = (float*)(smem + SM_C2V);
    float* cls = (float*)(smem + SM_CLS);
    uint32_t Xhi = smem_u32(smem + SM_XHI), Xlo = smem_u32(smem + SM_XLO);
    uint32_t Hh = smem_u32(smem + SM_HH);
    uint32_t Wt = smem_u32(smem + SM_W);

    int sel = s * NT + d_best_t[s];
    float bprob = d_best_prob[s];
    float c2sc = c2g[sel];

    if (tid < DK) {
        b1s[tid] = b1g[sel * DK + tid];
        b2s[tid] = b2g[sel * DK + tid];
        c1s[tid] = c1g[sel * DK + tid];
        c2v[tid] = C2g[(size_t)sel * DK + tid];
    }

    // W1 into smem + gather X -> fp16 hi/lo padded tiles
    copy_w(smem, s, 0, tid);
    {
        int xr = tid >> 1, xh = tid & 1;
        bool valid = xr < rows;
        int g = valid ? perm[xr] : 0;
        const float4* src = (const float4*)(states + (size_t)g * DK + xh * 64);
        uint32_t base0 = xr * SBB + xh * 128;
#pragma unroll
        for (int j8 = 0; j8 < 8; j8++) {
            float4 a = valid ? src[j8 * 2] : make_float4(0, 0, 0, 0);
            float4 c = valid ? src[j8 * 2 + 1] : make_float4(0, 0, 0, 0);
            uint4 hi, lo;
            split2h(a.x, a.y, hi.x, lo.x);
            split2h(a.z, a.w, hi.y, lo.y);
            split2h(c.x, c.y, hi.z, lo.z);
            split2h(c.z, c.w, hi.w, lo.w);
            uint32_t off = base0 + j8 * 16;
            *(uint4*)(smem + SM_XHI + off) = hi;
            *(uint4*)(smem + SM_XLO + off) = lo;
        }
    }
    __syncthreads();

    float acc[2][8][4];

    // ================= Pass 1: D = X @ W1, H = relu(D + b1) -> fp16 =================
    gemm_pass<2>(Xhi, Xlo, Wt, acc, wm, wn, lane);
    __syncthreads();               // all warps done reading W1 tile
    copy_w(smem, s, 1, tid);       // C1 into W tile (disjoint from H writes)
#pragma unroll
    for (int mt = 0; mt < 2; mt++) {
#pragma unroll
        for (int rh = 0; rh < 2; rh++) {
            int r = wm * 32 + mt * 16 + rh * 8 + gID;
            uint32_t roff = r * SBB;
#pragma unroll
            for (int ng = 0; ng < 8; ng++) {
                int c = wn * 64 + ng * 8 + 2 * tig;
                float v0 = fmaxf(acc[mt][ng][rh * 2 + 0] + b1s[c], 0.f);
                float v1 = fmaxf(acc[mt][ng][rh * 2 + 1] + b1s[c + 1], 0.f);
                __half2 hp = __halves2half2(__float2half_rn(v0), __float2half_rn(v1));
                *(uint32_t*)(smem + SM_HH + roff + c * 2) =
                    *reinterpret_cast<uint32_t*>(&hp);
            }
        }
    }
    __syncthreads();

    // ================= Pass 2: D = X @ C1 (classifier) =================
    gemm_pass<2>(Xhi, Xlo, Wt, acc, wm, wn, lane);
#pragma unroll
    for (int mt = 0; mt < 2; mt++) {
#pragma unroll
        for (int rh = 0; rh < 2; rh++) {
            float p = 0.f;
#pragma unroll
            for (int ng = 0; ng < 8; ng++) {
                int c = wn * 64 + ng * 8 + 2 * tig;
                p += fmaxf(acc[mt][ng][rh * 2 + 0] + c1s[c], 0.f) * c2v[c];
                p += fmaxf(acc[mt][ng][rh * 2 + 1] + c1s[c + 1], 0.f) * c2v[c + 1];
            }
            p += __shfl_xor_sync(0xffffffffu, p, 1);
            p += __shfl_xor_sync(0xffffffffu, p, 2);
            if (tig == 0) {
                int r = wm * 32 + mt * 16 + rh * 8 + gID;
                cls[wn * 128 + r] = p;
            }
        }
    }
    __syncthreads();               // cls visible; all warps done reading C1
    copy_w(smem, s, 2, tid);       // W2 into W tile
    if (tid < TM && tid < rows) {
        int g = perm[tid];
        float tot = cls[tid] + cls[128 + tid] + c2sc;
        float cv = 1.0f / (1.0f + expf(-tot));
        float ns = fminf(scores[g], cv);
        out[(size_t)n * DK + g]     = ns;     // out_score
        out[(size_t)n * DK + n + g] = bprob;  // item_prob
    }
    __syncthreads();

    // ================= Pass 3: D = H @ W2, out_state = D + b2 =================
    gemm_pass<1>(Hh, Hh, Wt, acc, wm, wn, lane);
#pragma unroll
    for (int mt = 0; mt < 2; mt++) {
#pragma unroll
        for (int rh = 0; rh < 2; rh++) {
            int r = wm * 32 + mt * 16 + rh * 8 + gID;
            if (r < rows) {
                int g = perm[r];
                float* dst = out + (size_t)g * DK;
#pragma unroll
                for (int ng = 0; ng < 8; ng++) {
                    int c = wn * 64 + ng * 8 + 2 * tig;
                    float2 v;
                    v.x = acc[mt][ng][rh * 2 + 0] + b2s[c];
                    v.y = acc[mt][ng][rh * 2 + 1] + b2s[c + 1];
                    *(float2*)(dst + c) = v;
                }
            }
        }
    }
}

// ============================================================
// launch
// ============================================================
extern "C" void kernel_launch(void* const* d_in, const int* in_sizes, int n_in,
                              void* d_out, int out_size) {
    const float* states = (const float*)d_in[0];
    const float* scores = (const float*)d_in[1];
    const int*   tids   = (const int*)d_in[2];
    const float* tmatch = (const float*)d_in[3];
    const float* W1 = (const float*)d_in[4];
    const float* b1 = (const float*)d_in[5];
    const float* W2 = (const float*)d_in[6];
    const float* b2 = (const float*)d_in[7];
    const float* C1 = (const float*)d_in[8];
    const float* c1 = (const float*)d_in[9];
    const float* C2 = (const float*)d_in[10];
    const float* c2 = (const float*)d_in[11];
    float* out = (float*)d_out;
    int n = in_sizes[2];

    cudaFuncSetAttribute(mlp_kernel, cudaFuncAttributeMaxDynamicSharedMemorySize, SM_TOTAL);

    int nblk = (n + 255) / 256;
    int tps = (n + TM - 1) / TM;   // worst-case tiles per type
    setup_kernel<<<1, 32>>>(tmatch);
    scatter_kernel<<<nblk, 256>>>(tids, n);
    prep_kernel<<<48, 256>>>(W1, C1, W2);
    mlp_kernel<<<NS * tps, NTH, SM_TOTAL>>>(states, scores, b1, b2, c1, C2, c2,
                                            out, n, tps);
}